// round 11
// baseline (speedup 1.0000x reference)
#include <cuda_runtime.h>
#include <math_constants.h>

#define SDIM 2048
#define BDIM 32
#define HDIM 1024

#define KS 16          // k-splits
#define KT (HDIM / KS) // 64 k per split
#define HT 128         // h per block tile (8 tiles)

#define FIX_SCALE 17592186044416.0f      // 2^44
#define FIX_INV   (1.0f / 17592186044416.0f)

// Scratch (no device allocs allowed). g_ufix is zero at rest: statically
// zero-initialized, and softmax re-zeros it each run -> graph-replayable.
__device__ unsigned long long g_ufix[BDIM * HDIM];  // fixed-point u accumulators
__device__ float g_scores[BDIM * SDIM];             // scores[b,s]

// ---------------------------------------------------------------------------
// Kernel 1: split-K tiled GEMM u = hidden @ W. grid (8 h-tiles, 16 k-splits),
// 512 threads. Partials merged via DETERMINISTIC int64 fixed-point atomicAdd
// (integer addition is associative+commutative -> order-independent).
// ---------------------------------------------------------------------------
__global__ __launch_bounds__(512) void proj_kernel(
    const float* __restrict__ hidden, const float* __restrict__ W) {
    __shared__ float4 sW[KT * (HT / 4)];   // 64k x 32 float4 = 32 KB
    __shared__ float  sH[BDIM * KT];       // 32b x 64k       = 8 KB

    const int h0 = blockIdx.x * HT;
    const int k0 = blockIdx.y * KT;
    const int tid = threadIdx.x;

    const float4* __restrict__ Wg = reinterpret_cast<const float4*>(W);
#pragma unroll
    for (int i = 0; i < (KT * HT / 4) / 512; ++i) {   // 4 iters
        int idx = tid + i * 512;
        int kk = idx >> 5;
        int c  = idx & 31;
        sW[idx] = Wg[(size_t)(k0 + kk) * (HDIM / 4) + (h0 >> 2) + c];
    }
#pragma unroll
    for (int i = 0; i < (BDIM * KT) / 512; ++i) {     // 4 iters
        int idx = tid + i * 512;
        int bb = idx >> 6;
        int kk = idx & 63;
        sH[idx] = hidden[bb * HDIM + k0 + kk];
    }
    __syncthreads();

    const int lane = tid & 31;          // h4 index (128 h / 4)
    const int b0 = (tid >> 5) * 2;      // 16 warps x 2 b = 32 b

    float4 acc0 = {0,0,0,0}, acc1 = {0,0,0,0};
#pragma unroll 16
    for (int k = 0; k < KT; ++k) {
        float4 w4 = sW[k * 32 + lane];
        float h0v = sH[(b0 + 0) * KT + k];
        float h1v = sH[(b0 + 1) * KT + k];
        acc0.x = fmaf(h0v, w4.x, acc0.x); acc0.y = fmaf(h0v, w4.y, acc0.y);
        acc0.z = fmaf(h0v, w4.z, acc0.z); acc0.w = fmaf(h0v, w4.w, acc0.w);
        acc1.x = fmaf(h1v, w4.x, acc1.x); acc1.y = fmaf(h1v, w4.y, acc1.y);
        acc1.z = fmaf(h1v, w4.z, acc1.z); acc1.w = fmaf(h1v, w4.w, acc1.w);
    }

    // Fixed-point deterministic accumulation (wraparound-safe mod 2^64).
    const int hb = h0 + lane * 4;
    unsigned long long* __restrict__ uf0 = g_ufix + (b0 + 0) * HDIM + hb;
    unsigned long long* __restrict__ uf1 = g_ufix + (b0 + 1) * HDIM + hb;
    atomicAdd(uf0 + 0, (unsigned long long)__float2ll_rn(acc0.x * FIX_SCALE));
    atomicAdd(uf0 + 1, (unsigned long long)__float2ll_rn(acc0.y * FIX_SCALE));
    atomicAdd(uf0 + 2, (unsigned long long)__float2ll_rn(acc0.z * FIX_SCALE));
    atomicAdd(uf0 + 3, (unsigned long long)__float2ll_rn(acc0.w * FIX_SCALE));
    atomicAdd(uf1 + 0, (unsigned long long)__float2ll_rn(acc1.x * FIX_SCALE));
    atomicAdd(uf1 + 1, (unsigned long long)__float2ll_rn(acc1.y * FIX_SCALE));
    atomicAdd(uf1 + 2, (unsigned long long)__float2ll_rn(acc1.z * FIX_SCALE));
    atomicAdd(uf1 + 3, (unsigned long long)__float2ll_rn(acc1.w * FIX_SCALE));
}

// ---------------------------------------------------------------------------
// Kernel 2: scores[b,s] = u[b] . enc[s,b,:] — pure 268 MB HBM stream.
// u decoded from fixed-point on the fly (L2-resident, cvts hidden by DRAM).
// ---------------------------------------------------------------------------
__global__ __launch_bounds__(256) void score_kernel(const float* __restrict__ enc) {
    const int warp = (blockIdx.x * blockDim.x + threadIdx.x) >> 5;
    const int lane = threadIdx.x & 31;
    if (warp >= SDIM * BDIM) return;

    const int b = warp & (BDIM - 1);
    const int s = warp >> 5;

    const float4* __restrict__ erow =
        reinterpret_cast<const float4*>(enc + (size_t)warp * HDIM);
    const ulonglong2* __restrict__ uq =
        reinterpret_cast<const ulonglong2*>(g_ufix + b * HDIM);

    float acc = 0.0f;
#pragma unroll
    for (int j = 0; j < 8; ++j) {
        float4 e = __ldcs(&erow[j * 32 + lane]);            // streaming
        ulonglong2 q0 = __ldg(&uq[2 * (j * 32 + lane)]);    // cached
        ulonglong2 q1 = __ldg(&uq[2 * (j * 32 + lane) + 1]);
        float ux = __ll2float_rn((long long)q0.x) * FIX_INV;
        float uy = __ll2float_rn((long long)q0.y) * FIX_INV;
        float uz = __ll2float_rn((long long)q1.x) * FIX_INV;
        float uw = __ll2float_rn((long long)q1.y) * FIX_INV;
        acc = fmaf(e.x, ux, acc);
        acc = fmaf(e.y, uy, acc);
        acc = fmaf(e.z, uz, acc);
        acc = fmaf(e.w, uw, acc);
    }
#pragma unroll
    for (int off = 16; off > 0; off >>= 1)
        acc += __shfl_xor_sync(0xFFFFFFFFu, acc, off);

    if (lane == 0) g_scores[b * SDIM + s] = acc;
}

// ---------------------------------------------------------------------------
// Kernel 3: softmax over s per b (32 blocks x 1024 threads). Also re-zeros
// g_ufix for the next graph replay (this kernel is work-insensitive: its ~5us
// is launch/drain-bound, proven in R3/R4).
// ---------------------------------------------------------------------------
__global__ __launch_bounds__(1024) void softmax_kernel(float* __restrict__ out) {
    const int b = blockIdx.x;
    const int tid = threadIdx.x;
    const float* __restrict__ row = g_scores + b * SDIM;

    g_ufix[b * HDIM + tid] = 0ull;   // reset accumulators for next replay

    __shared__ float sred[32];

    float v0 = row[tid];
    float v1 = row[tid + 1024];
    float vmax = fmaxf(v0, v1);
#pragma unroll
    for (int off = 16; off > 0; off >>= 1)
        vmax = fmaxf(vmax, __shfl_xor_sync(0xFFFFFFFFu, vmax, off));
    if ((tid & 31) == 0) sred[tid >> 5] = vmax;
    __syncthreads();
    if (tid < 32) {
        float v = sred[tid];
#pragma unroll
        for (int off = 16; off > 0; off >>= 1)
            v = fmaxf(v, __shfl_xor_sync(0xFFFFFFFFu, v, off));
        sred[0] = v;
    }
    __syncthreads();
    vmax = sred[0];
    __syncthreads();

    v0 = __expf(v0 - vmax);
    v1 = __expf(v1 - vmax);
    float lsum = v0 + v1;
#pragma unroll
    for (int off = 16; off > 0; off >>= 1)
        lsum += __shfl_xor_sync(0xFFFFFFFFu, lsum, off);
    if ((tid & 31) == 0) sred[tid >> 5] = lsum;
    __syncthreads();
    if (tid < 32) {
        float v = sred[tid];
#pragma unroll
        for (int off = 16; off > 0; off >>= 1)
            v += __shfl_xor_sync(0xFFFFFFFFu, v, off);
        sred[0] = v;
    }
    __syncthreads();
    const float inv = 1.0f / sred[0];

    out[b * SDIM + tid]        = v0 * inv;
    out[b * SDIM + tid + 1024] = v1 * inv;
}

// ---------------------------------------------------------------------------
extern "C" void kernel_launch(void* const* d_in, const int* in_sizes, int n_in,
                              void* d_out, int out_size) {
    const float* hidden = (const float*)d_in[0];  // [B,H]
    const float* enc    = (const float*)d_in[1];  // [S,B,H]
    const float* W      = (const float*)d_in[2];  // [H,H]
    float* out = (float*)d_out;                   // [1,B,S]

    dim3 pg(HDIM / HT, KS);                       // (8, 16) = 128 blocks
    proj_kernel<<<pg, 512>>>(hidden, W);

    const int total_warps = SDIM * BDIM;          // 65536
    score_kernel<<<total_warps * 32 / 256, 256>>>(enc);

    softmax_kernel<<<BDIM, 1024>>>(out);
}

// round 12
// speedup vs baseline: 2.3293x; 2.3293x over previous
#include <cuda_runtime.h>
#include <math_constants.h>

#define SDIM 2048
#define BDIM 32
#define HDIM 1024

#define KS 16          // k-splits
#define KT (HDIM / KS) // 64 k per split
#define HT 64          // h per block tile (16 tiles) -> 256 blocks, 2/SM

// Scratch (no device allocs allowed)
__device__ float g_part[KS * BDIM * HDIM];  // split-K partials (2 MB)
__device__ float g_u[BDIM * HDIM];          // u = hidden @ W
__device__ float g_scores[BDIM * SDIM];     // scores[b,s]

// ---------------------------------------------------------------------------
// Kernel 1: split-K tiled GEMM u_part = hidden[:, krange] @ W[krange, htile]
// grid (16 h-tiles, 16 k-splits) = 256 blocks, 256 threads => 2 blocks/SM,
// overlapping each block's smem-fill latency with the other's compute.
// Each thread: 2 b x 4 h outputs, 64-deep k loop.
// ---------------------------------------------------------------------------
__global__ __launch_bounds__(256) void proj_kernel(
    const float* __restrict__ hidden, const float* __restrict__ W) {
    __shared__ float4 sW[KT * (HT / 4)];   // 64k x 16 float4 = 16 KB
    __shared__ float  sH[BDIM * KT];       // 32b x 64k       = 8 KB

    const int h0 = blockIdx.x * HT;
    const int k0 = blockIdx.y * KT;
    const int tid = threadIdx.x;

    // Load W tile: 64 rows x 16 float4, coalesced. 1024 float4 / 256 thr = 4.
    const float4* __restrict__ Wg = reinterpret_cast<const float4*>(W);
#pragma unroll
    for (int i = 0; i < (KT * HT / 4) / 256; ++i) {   // 4 iters
        int idx = tid + i * 256;
        int kk = idx >> 4;                            // /16
        int c  = idx & 15;
        sW[idx] = Wg[(size_t)(k0 + kk) * (HDIM / 4) + (h0 >> 2) + c];
    }
    // Load hidden tile: 32 b x 64 k. 2048 / 256 = 8 iters.
#pragma unroll
    for (int i = 0; i < (BDIM * KT) / 256; ++i) {
        int idx = tid + i * 256;
        int bb = idx >> 6;
        int kk = idx & 63;
        sH[idx] = hidden[bb * HDIM + k0 + kk];
    }
    __syncthreads();

    const int hi = tid & 15;            // float4-h index within 64-h tile
    const int b0 = (tid >> 4) * 2;      // 16 groups x 2 b = 32 b

    float4 acc0 = {0,0,0,0}, acc1 = {0,0,0,0};
#pragma unroll 16
    for (int k = 0; k < KT; ++k) {
        float4 w4 = sW[k * 16 + hi];
        float h0v = sH[(b0 + 0) * KT + k];
        float h1v = sH[(b0 + 1) * KT + k];
        acc0.x = fmaf(h0v, w4.x, acc0.x); acc0.y = fmaf(h0v, w4.y, acc0.y);
        acc0.z = fmaf(h0v, w4.z, acc0.z); acc0.w = fmaf(h0v, w4.w, acc0.w);
        acc1.x = fmaf(h1v, w4.x, acc1.x); acc1.y = fmaf(h1v, w4.y, acc1.y);
        acc1.z = fmaf(h1v, w4.z, acc1.z); acc1.w = fmaf(h1v, w4.w, acc1.w);
    }

    float4* __restrict__ part4 = reinterpret_cast<float4*>(
        g_part + (size_t)blockIdx.y * BDIM * HDIM);
    const int hbase4 = (h0 >> 2) + hi;
    part4[(b0 + 0) * (HDIM / 4) + hbase4] = acc0;
    part4[(b0 + 1) * (HDIM / 4) + hbase4] = acc1;
}

// ---------------------------------------------------------------------------
// Kernel 1b: fold split-K partials (fixed order -> deterministic).
// __ldcs: read-once, keep L2 clean for g_u and the stream.
// ---------------------------------------------------------------------------
__global__ __launch_bounds__(256) void reduce_kernel() {
    const int idx4 = blockIdx.x * 256 + threadIdx.x;   // float4 idx, 0..8191
    float4 s4 = {0, 0, 0, 0};
#pragma unroll
    for (int j = 0; j < KS; ++j) {
        float4 p = __ldcs(reinterpret_cast<const float4*>(
            g_part + (size_t)j * BDIM * HDIM) + idx4);
        s4.x += p.x; s4.y += p.y; s4.z += p.z; s4.w += p.w;
    }
    reinterpret_cast<float4*>(g_u)[idx4] = s4;
}

// ---------------------------------------------------------------------------
// Kernel 2: scores[b,s] = u[b] . enc[s,b,:] — pure 268 MB HBM stream.
// Proven form (~7.2 TB/s): no atomics, no prologue, no tail, no decode.
// ---------------------------------------------------------------------------
__global__ __launch_bounds__(256) void score_kernel(const float* __restrict__ enc) {
    const int warp = (blockIdx.x * blockDim.x + threadIdx.x) >> 5;
    const int lane = threadIdx.x & 31;
    if (warp >= SDIM * BDIM) return;

    const int b = warp & (BDIM - 1);
    const int s = warp >> 5;

    const float4* __restrict__ erow =
        reinterpret_cast<const float4*>(enc + (size_t)warp * HDIM);
    const float4* __restrict__ urow =
        reinterpret_cast<const float4*>(g_u + b * HDIM);

    float acc = 0.0f;
#pragma unroll
    for (int j = 0; j < 8; ++j) {
        float4 e = __ldcs(&erow[j * 32 + lane]);   // streaming, evict-first
        float4 u = __ldg(&urow[j * 32 + lane]);    // cached, L1/L2-resident
        acc = fmaf(e.x, u.x, acc);
        acc = fmaf(e.y, u.y, acc);
        acc = fmaf(e.z, u.z, acc);
        acc = fmaf(e.w, u.w, acc);
    }
#pragma unroll
    for (int off = 16; off > 0; off >>= 1)
        acc += __shfl_xor_sync(0xFFFFFFFFu, acc, off);

    if (lane == 0) g_scores[b * SDIM + s] = acc;
}

// ---------------------------------------------------------------------------
// Kernel 3: softmax over s per b. 32 blocks x 1024 threads.
// (hidden.bias term is constant per b -> invariant under softmax -> dropped.)
// ---------------------------------------------------------------------------
__global__ __launch_bounds__(1024) void softmax_kernel(float* __restrict__ out) {
    const int b = blockIdx.x;
    const int tid = threadIdx.x;
    const float* __restrict__ row = g_scores + b * SDIM;

    __shared__ float sred[32];

    float v0 = row[tid];
    float v1 = row[tid + 1024];
    float vmax = fmaxf(v0, v1);
#pragma unroll
    for (int off = 16; off > 0; off >>= 1)
        vmax = fmaxf(vmax, __shfl_xor_sync(0xFFFFFFFFu, vmax, off));
    if ((tid & 31) == 0) sred[tid >> 5] = vmax;
    __syncthreads();
    if (tid < 32) {
        float v = sred[tid];
#pragma unroll
        for (int off = 16; off > 0; off >>= 1)
            v = fmaxf(v, __shfl_xor_sync(0xFFFFFFFFu, v, off));
        sred[0] = v;
    }
    __syncthreads();
    vmax = sred[0];
    __syncthreads();

    v0 = __expf(v0 - vmax);
    v1 = __expf(v1 - vmax);
    float lsum = v0 + v1;
#pragma unroll
    for (int off = 16; off > 0; off >>= 1)
        lsum += __shfl_xor_sync(0xFFFFFFFFu, lsum, off);
    if ((tid & 31) == 0) sred[tid >> 5] = lsum;
    __syncthreads();
    if (tid < 32) {
        float v = sred[tid];
#pragma unroll
        for (int off = 16; off > 0; off >>= 1)
            v += __shfl_xor_sync(0xFFFFFFFFu, v, off);
        sred[0] = v;
    }
    __syncthreads();
    const float inv = 1.0f / sred[0];

    out[b * SDIM + tid]        = v0 * inv;
    out[b * SDIM + tid + 1024] = v1 * inv;
}

// ---------------------------------------------------------------------------
extern "C" void kernel_launch(void* const* d_in, const int* in_sizes, int n_in,
                              void* d_out, int out_size) {
    const float* hidden = (const float*)d_in[0];  // [B,H]
    const float* enc    = (const float*)d_in[1];  // [S,B,H]
    const float* W      = (const float*)d_in[2];  // [H,H]
    float* out = (float*)d_out;                   // [1,B,S]

    dim3 pg(HDIM / HT, KS);                       // (16, 16) = 256 blocks
    proj_kernel<<<pg, 256>>>(hidden, W);
    reduce_kernel<<<(BDIM * HDIM / 4) / 256, 256>>>();   // 32 blocks

    const int total_warps = SDIM * BDIM;          // 65536
    score_kernel<<<total_warps * 32 / 256, 256>>>(enc);

    softmax_kernel<<<BDIM, 1024>>>(out);
}

// round 13
// speedup vs baseline: 2.4079x; 1.0337x over previous
#include <cuda_runtime.h>
#include <math_constants.h>

#define SDIM 2048
#define BDIM 32
#define HDIM 1024

#define KS 16          // k-splits
#define KT (HDIM / KS) // 64 k per split
#define HT 128         // h per block tile (8 tiles)

// Scratch (no device allocs allowed)
__device__ float g_part[KS * BDIM * HDIM];  // split-K partials (2 MB)
__device__ float g_u[BDIM * HDIM];          // u = hidden @ W
__device__ float g_scores[BDIM * SDIM];     // scores[b,s]

// --- PDL primitives -------------------------------------------------------
__device__ __forceinline__ void grid_wait() {
    asm volatile("griddepcontrol.wait;" ::: "memory");
}
__device__ __forceinline__ void grid_trigger() {
    asm volatile("griddepcontrol.launch_dependents;");
}

// ---------------------------------------------------------------------------
// Kernel 1: split-K tiled GEMM u_part = hidden[:, krange] @ W[krange, htile]
// grid (8 h-tiles, 16 k-splits) = 128 blocks, 512 threads.
// ---------------------------------------------------------------------------
__global__ __launch_bounds__(512) void proj_kernel(
    const float* __restrict__ hidden, const float* __restrict__ W) {
    __shared__ float4 sW[KT * (HT / 4)];   // 32 KB
    __shared__ float  sH[BDIM * KT];       // 8 KB

    const int h0 = blockIdx.x * HT;
    const int k0 = blockIdx.y * KT;
    const int tid = threadIdx.x;

    const float4* __restrict__ Wg = reinterpret_cast<const float4*>(W);
#pragma unroll
    for (int i = 0; i < (KT * HT / 4) / 512; ++i) {   // 4 iters
        int idx = tid + i * 512;
        int kk = idx >> 5;
        int c  = idx & 31;
        sW[idx] = Wg[(size_t)(k0 + kk) * (HDIM / 4) + (h0 >> 2) + c];
    }
#pragma unroll
    for (int i = 0; i < (BDIM * KT) / 512; ++i) {     // 4 iters
        int idx = tid + i * 512;
        int bb = idx >> 6;
        int kk = idx & 63;
        sH[idx] = hidden[bb * HDIM + k0 + kk];
    }
    __syncthreads();

    const int lane = tid & 31;
    const int b0 = (tid >> 5) * 2;      // 16 warps x 2 b

    float4 acc0 = {0,0,0,0}, acc1 = {0,0,0,0};
#pragma unroll 16
    for (int k = 0; k < KT; ++k) {
        float4 w4 = sW[k * 32 + lane];
        float h0v = sH[(b0 + 0) * KT + k];
        float h1v = sH[(b0 + 1) * KT + k];
        acc0.x = fmaf(h0v, w4.x, acc0.x); acc0.y = fmaf(h0v, w4.y, acc0.y);
        acc0.z = fmaf(h0v, w4.z, acc0.z); acc0.w = fmaf(h0v, w4.w, acc0.w);
        acc1.x = fmaf(h1v, w4.x, acc1.x); acc1.y = fmaf(h1v, w4.y, acc1.y);
        acc1.z = fmaf(h1v, w4.z, acc1.z); acc1.w = fmaf(h1v, w4.w, acc1.w);
    }

    float4* __restrict__ part4 = reinterpret_cast<float4*>(
        g_part + (size_t)blockIdx.y * BDIM * HDIM);
    const int hbase4 = (h0 >> 2) + lane;
    part4[(b0 + 0) * (HDIM / 4) + hbase4] = acc0;
    part4[(b0 + 1) * (HDIM / 4) + hbase4] = acc1;

    grid_trigger();   // all stores issued -> release dependent (reduce)
}

// ---------------------------------------------------------------------------
// Kernel 1b: fold split-K partials (fixed order -> deterministic).
// ---------------------------------------------------------------------------
__global__ __launch_bounds__(256) void reduce_kernel() {
    grid_wait();   // proj's g_part fully visible

    const int idx4 = blockIdx.x * 256 + threadIdx.x;   // float4 idx, 0..8191
    float4 s4 = {0, 0, 0, 0};
#pragma unroll
    for (int j = 0; j < KS; ++j) {
        float4 p = __ldcs(reinterpret_cast<const float4*>(
            g_part + (size_t)j * BDIM * HDIM) + idx4);
        s4.x += p.x; s4.y += p.y; s4.z += p.z; s4.w += p.w;
    }
    reinterpret_cast<float4*>(g_u)[idx4] = s4;

    grid_trigger();   // g_u stores issued -> release dependent (score)
}

// ---------------------------------------------------------------------------
// Kernel 2: scores[b,s] = u[b] . enc[s,b,:] — pure 268 MB HBM stream.
// Proven form (~7.2 TB/s): no atomics, no prologue, no tail.
// ---------------------------------------------------------------------------
__global__ __launch_bounds__(256) void score_kernel(const float* __restrict__ enc) {
    grid_wait();   // g_u fully visible

    const int warp = (blockIdx.x * blockDim.x + threadIdx.x) >> 5;
    const int lane = threadIdx.x & 31;

    const int b = warp & (BDIM - 1);
    const int s = warp >> 5;

    const float4* __restrict__ erow =
        reinterpret_cast<const float4*>(enc + (size_t)warp * HDIM);
    const float4* __restrict__ urow =
        reinterpret_cast<const float4*>(g_u + b * HDIM);

    float acc = 0.0f;
#pragma unroll
    for (int j = 0; j < 8; ++j) {
        float4 e = __ldcs(&erow[j * 32 + lane]);   // streaming, evict-first
        float4 u = __ldg(&urow[j * 32 + lane]);    // cached, L1/L2-resident
        acc = fmaf(e.x, u.x, acc);
        acc = fmaf(e.y, u.y, acc);
        acc = fmaf(e.z, u.z, acc);
        acc = fmaf(e.w, u.w, acc);
    }
#pragma unroll
    for (int off = 16; off > 0; off >>= 1)
        acc += __shfl_xor_sync(0xFFFFFFFFu, acc, off);

    if (lane == 0) g_scores[b * SDIM + s] = acc;

    grid_trigger();   // g_scores issued -> release dependent (softmax)
}

// ---------------------------------------------------------------------------
// Kernel 3: softmax over s per b. 32 blocks x 1024 threads — pre-launched
// via PDL, starts the moment score's stores are visible.
// ---------------------------------------------------------------------------
__global__ __launch_bounds__(1024) void softmax_kernel(float* __restrict__ out) {
    grid_wait();   // g_scores fully visible

    const int b = blockIdx.x;
    const int tid = threadIdx.x;
    const float* __restrict__ row = g_scores + b * SDIM;

    __shared__ float sred[32];

    float v0 = row[tid];
    float v1 = row[tid + 1024];
    float vmax = fmaxf(v0, v1);
#pragma unroll
    for (int off = 16; off > 0; off >>= 1)
        vmax = fmaxf(vmax, __shfl_xor_sync(0xFFFFFFFFu, vmax, off));
    if ((tid & 31) == 0) sred[tid >> 5] = vmax;
    __syncthreads();
    if (tid < 32) {
        float v = sred[tid];
#pragma unroll
        for (int off = 16; off > 0; off >>= 1)
            v = fmaxf(v, __shfl_xor_sync(0xFFFFFFFFu, v, off));
        sred[0] = v;
    }
    __syncthreads();
    vmax = sred[0];
    __syncthreads();

    v0 = __expf(v0 - vmax);
    v1 = __expf(v1 - vmax);
    float lsum = v0 + v1;
#pragma unroll
    for (int off = 16; off > 0; off >>= 1)
        lsum += __shfl_xor_sync(0xFFFFFFFFu, lsum, off);
    if ((tid & 31) == 0) sred[tid >> 5] = lsum;
    __syncthreads();
    if (tid < 32) {
        float v = sred[tid];
#pragma unroll
        for (int off = 16; off > 0; off >>= 1)
            v += __shfl_xor_sync(0xFFFFFFFFu, v, off);
        sred[0] = v;
    }
    __syncthreads();
    const float inv = 1.0f / sred[0];

    out[b * SDIM + tid]        = v0 * inv;
    out[b * SDIM + tid + 1024] = v1 * inv;
}

// ---------------------------------------------------------------------------
extern "C" void kernel_launch(void* const* d_in, const int* in_sizes, int n_in,
                              void* d_out, int out_size) {
    const float* hidden = (const float*)d_in[0];  // [B,H]
    const float* enc    = (const float*)d_in[1];  // [S,B,H]
    const float* W      = (const float*)d_in[2];  // [H,H]
    float* out = (float*)d_out;                   // [1,B,S]

    // First kernel: ordinary launch.
    dim3 pg(HDIM / HT, KS);                       // (8, 16)
    proj_kernel<<<pg, 512>>>(hidden, W);

    // Dependent kernels: Programmatic Dependent Launch -> pre-launched,
    // spinning in griddepcontrol.wait while the predecessor drains.
    cudaLaunchAttribute pdl[1];
    pdl[0].id = cudaLaunchAttributeProgrammaticStreamSerialization;
    pdl[0].val.programmaticStreamSerializationAllowed = 1;

    cudaLaunchConfig_t cfg = {};
    cfg.stream = 0;
    cfg.attrs = pdl;
    cfg.numAttrs = 1;

    cfg.gridDim = dim3((BDIM * HDIM / 4) / 256);  // 32 blocks
    cfg.blockDim = dim3(256);
    cudaLaunchKernelEx(&cfg, reduce_kernel);

    cfg.gridDim = dim3(SDIM * BDIM / 8);          // 8192 blocks
    cfg.blockDim = dim3(256);
    cudaLaunchKernelEx(&cfg, score_kernel, enc);

    cfg.gridDim = dim3(BDIM);                     // 32 blocks
    cfg.blockDim = dim3(1024);
    cudaLaunchKernelEx(&cfg, softmax_kernel, out);
}

// round 14
// speedup vs baseline: 2.5016x; 1.0389x over previous
#include <cuda_runtime.h>
#include <math_constants.h>

#define SDIM 2048
#define BDIM 32
#define HDIM 1024

#define KS 16          // k-splits
#define KT (HDIM / KS) // 64 k per split
#define HT 128         // h per block tile (8 tiles)

// Scratch (no device allocs allowed)
__device__ float g_part[KS * BDIM * HDIM];  // split-K partials (2 MB)
__device__ float g_u[BDIM * HDIM];          // u = hidden @ W
__device__ float g_scores[BDIM * SDIM];     // scores[b,s]

// --- PDL primitives -------------------------------------------------------
__device__ __forceinline__ void grid_wait() {
    asm volatile("griddepcontrol.wait;" ::: "memory");
}
__device__ __forceinline__ void grid_trigger() {
    asm volatile("griddepcontrol.launch_dependents;");
}

// ---------------------------------------------------------------------------
// Kernel 1: split-K tiled GEMM u_part = hidden[:, krange] @ W[krange, htile]
// grid (8 h-tiles, 16 k-splits) = 128 blocks, 512 threads.
// Triggers dependents at ENTRY: reduce/score launch + prefetch while we run.
// ---------------------------------------------------------------------------
__global__ __launch_bounds__(512) void proj_kernel(
    const float* __restrict__ hidden, const float* __restrict__ W) {
    grid_trigger();   // release chain immediately (consumers gate on grid_wait)

    __shared__ float4 sW[KT * (HT / 4)];   // 32 KB
    __shared__ float  sH[BDIM * KT];       // 8 KB

    const int h0 = blockIdx.x * HT;
    const int k0 = blockIdx.y * KT;
    const int tid = threadIdx.x;

    const float4* __restrict__ Wg = reinterpret_cast<const float4*>(W);
#pragma unroll
    for (int i = 0; i < (KT * HT / 4) / 512; ++i) {   // 4 iters
        int idx = tid + i * 512;
        int kk = idx >> 5;
        int c  = idx & 31;
        sW[idx] = Wg[(size_t)(k0 + kk) * (HDIM / 4) + (h0 >> 2) + c];
    }
#pragma unroll
    for (int i = 0; i < (BDIM * KT) / 512; ++i) {     // 4 iters
        int idx = tid + i * 512;
        int bb = idx >> 6;
        int kk = idx & 63;
        sH[idx] = hidden[bb * HDIM + k0 + kk];
    }
    __syncthreads();

    const int lane = tid & 31;
    const int b0 = (tid >> 5) * 2;      // 16 warps x 2 b

    float4 acc0 = {0,0,0,0}, acc1 = {0,0,0,0};
#pragma unroll 16
    for (int k = 0; k < KT; ++k) {
        float4 w4 = sW[k * 32 + lane];
        float h0v = sH[(b0 + 0) * KT + k];
        float h1v = sH[(b0 + 1) * KT + k];
        acc0.x = fmaf(h0v, w4.x, acc0.x); acc0.y = fmaf(h0v, w4.y, acc0.y);
        acc0.z = fmaf(h0v, w4.z, acc0.z); acc0.w = fmaf(h0v, w4.w, acc0.w);
        acc1.x = fmaf(h1v, w4.x, acc1.x); acc1.y = fmaf(h1v, w4.y, acc1.y);
        acc1.z = fmaf(h1v, w4.z, acc1.z); acc1.w = fmaf(h1v, w4.w, acc1.w);
    }

    float4* __restrict__ part4 = reinterpret_cast<float4*>(
        g_part + (size_t)blockIdx.y * BDIM * HDIM);
    const int hbase4 = (h0 >> 2) + lane;
    part4[(b0 + 0) * (HDIM / 4) + hbase4] = acc0;
    part4[(b0 + 1) * (HDIM / 4) + hbase4] = acc1;
}

// ---------------------------------------------------------------------------
// Kernel 1b: fold split-K partials (fixed order -> deterministic).
// Triggers at entry (score prefetches enc meanwhile); waits for proj's g_part.
// ---------------------------------------------------------------------------
__global__ __launch_bounds__(256) void reduce_kernel() {
    grid_trigger();   // release score immediately
    grid_wait();      // g_part fully visible

    const int idx4 = blockIdx.x * 256 + threadIdx.x;   // float4 idx, 0..8191
    float4 s4 = {0, 0, 0, 0};
#pragma unroll
    for (int j = 0; j < KS; ++j) {
        float4 p = __ldcs(reinterpret_cast<const float4*>(
            g_part + (size_t)j * BDIM * HDIM) + idx4);
        s4.x += p.x; s4.y += p.y; s4.z += p.z; s4.w += p.w;
    }
    reinterpret_cast<float4*>(g_u)[idx4] = s4;
}

// ---------------------------------------------------------------------------
// Kernel 2: scores[b,s] = u[b] . enc[s,b,:] — 268 MB HBM stream.
// enc loads hoisted BEFORE grid_wait: they don't depend on g_u, so resident
// waves stream enc while proj/reduce still run. u consumed after the wait.
// ---------------------------------------------------------------------------
__global__ __launch_bounds__(256) void score_kernel(const float* __restrict__ enc) {
    const int warp = (blockIdx.x * blockDim.x + threadIdx.x) >> 5;
    const int lane = threadIdx.x & 31;

    const int b = warp & (BDIM - 1);
    const int s = warp >> 5;

    const float4* __restrict__ erow =
        reinterpret_cast<const float4*>(enc + (size_t)warp * HDIM);

    // ---- prefetch: issue all enc loads before waiting on g_u ----
    float4 e[8];
#pragma unroll
    for (int j = 0; j < 8; ++j)
        e[j] = __ldcs(&erow[j * 32 + lane]);

    grid_wait();   // g_u fully visible (reduce complete)

    const float4* __restrict__ urow =
        reinterpret_cast<const float4*>(g_u + b * HDIM);

    float acc = 0.0f;
#pragma unroll
    for (int j = 0; j < 8; ++j) {
        float4 u = __ldg(&urow[j * 32 + lane]);    // cached, L1/L2-resident
        acc = fmaf(e[j].x, u.x, acc);
        acc = fmaf(e[j].y, u.y, acc);
        acc = fmaf(e[j].z, u.z, acc);
        acc = fmaf(e[j].w, u.w, acc);
    }
#pragma unroll
    for (int off = 16; off > 0; off >>= 1)
        acc += __shfl_xor_sync(0xFFFFFFFFu, acc, off);

    if (lane == 0) g_scores[b * SDIM + s] = acc;

    grid_trigger();   // g_scores issued -> release softmax
}

// ---------------------------------------------------------------------------
// Kernel 3: softmax over s per b. 32 blocks x 1024 threads, PDL-prelaunched.
// (hidden.bias term is constant per b -> invariant under softmax -> dropped.)
// ---------------------------------------------------------------------------
__global__ __launch_bounds__(1024) void softmax_kernel(float* __restrict__ out) {
    grid_wait();   // g_scores fully visible

    const int b = blockIdx.x;
    const int tid = threadIdx.x;
    const float* __restrict__ row = g_scores + b * SDIM;

    __shared__ float sred[32];

    float v0 = row[tid];
    float v1 = row[tid + 1024];
    float vmax = fmaxf(v0, v1);
#pragma unroll
    for (int off = 16; off > 0; off >>= 1)
        vmax = fmaxf(vmax, __shfl_xor_sync(0xFFFFFFFFu, vmax, off));
    if ((tid & 31) == 0) sred[tid >> 5] = vmax;
    __syncthreads();
    if (tid < 32) {
        float v = sred[tid];
#pragma unroll
        for (int off = 16; off > 0; off >>= 1)
            v = fmaxf(v, __shfl_xor_sync(0xFFFFFFFFu, v, off));
        sred[0] = v;
    }
    __syncthreads();
    vmax = sred[0];
    __syncthreads();

    v0 = __expf(v0 - vmax);
    v1 = __expf(v1 - vmax);
    float lsum = v0 + v1;
#pragma unroll
    for (int off = 16; off > 0; off >>= 1)
        lsum += __shfl_xor_sync(0xFFFFFFFFu, lsum, off);
    if ((tid & 31) == 0) sred[tid >> 5] = lsum;
    __syncthreads();
    if (tid < 32) {
        float v = sred[tid];
#pragma unroll
        for (int off = 16; off > 0; off >>= 1)
            v += __shfl_xor_sync(0xFFFFFFFFu, v, off);
        sred[0] = v;
    }
    __syncthreads();
    const float inv = 1.0f / sred[0];

    out[b * SDIM + tid]        = v0 * inv;
    out[b * SDIM + tid + 1024] = v1 * inv;
}

// ---------------------------------------------------------------------------
extern "C" void kernel_launch(void* const* d_in, const int* in_sizes, int n_in,
                              void* d_out, int out_size) {
    const float* hidden = (const float*)d_in[0];  // [B,H]
    const float* enc    = (const float*)d_in[1];  // [S,B,H]
    const float* W      = (const float*)d_in[2];  // [H,H]
    float* out = (float*)d_out;                   // [1,B,S]

    // First kernel: ordinary launch.
    dim3 pg(HDIM / HT, KS);                       // (8, 16)
    proj_kernel<<<pg, 512>>>(hidden, W);

    // Dependents: PDL — launched as soon as the predecessor triggers (entry),
    // gated for correctness by griddepcontrol.wait.
    cudaLaunchAttribute pdl[1];
    pdl[0].id = cudaLaunchAttributeProgrammaticStreamSerialization;
    pdl[0].val.programmaticStreamSerializationAllowed = 1;

    cudaLaunchConfig_t cfg = {};
    cfg.stream = 0;
    cfg.attrs = pdl;
    cfg.numAttrs = 1;

    cfg.gridDim = dim3((BDIM * HDIM / 4) / 256);  // 32 blocks
    cfg.blockDim = dim3(256);
    cudaLaunchKernelEx(&cfg, reduce_kernel);

    cfg.gridDim = dim3(SDIM * BDIM / 8);          // 8192 blocks
    cfg.blockDim = dim3(256);
    cudaLaunchKernelEx(&cfg, score_kernel, enc);

    cfg.gridDim = dim3(BDIM);                     // 32 blocks
    cfg.blockDim = dim3(1024);
    cudaLaunchKernelEx(&cfg, softmax_kernel, out);
}